// round 11
// baseline (speedup 1.0000x reference)
#include <cuda_runtime.h>
#include <math.h>
#include <stdint.h>

// ---------------------------------------------------------------------------
// DetectionLoss (FCOS-style) on GB300 — Round 11.
//  launch 1: k_bulk (focal0 over ALL logits and ALL objectness; grid verify)
//            [unchanged — measured DRAM-bound ~12us]
//  launch 2: k_pos3 (grid = (M/4) x B, 256 thr: 4 boxes/block, one 7x7 window
//                    cell per thread; corrections + positive losses; finalize)
// ---------------------------------------------------------------------------

#define MAX_M   64
#define MAX_WH  1024
#define BOX_PER_BLK 4

// accumulators: 0 obj, 1 cls, 2 ctr, 3 l1, 4 giou, 5 wsum
__device__ double g_acc[8];
__device__ unsigned int g_done;     // = 0
__device__ int g_ok = 1;            // grid-verified flag

// ---------------- math helpers -------------------------------------------

__device__ __forceinline__ float focal0(float x) {
    float e = __expf(-fabsf(x));
    float r = __fdividef(1.0f, 1.0f + e);
    float p = (x >= 0.0f) ? r : 1.0f - r;
    float sp = fmaxf(x, 0.0f) + __logf(1.0f + e);
    return 0.75f * sp * p * p;
}
__device__ __forceinline__ float focal1(float x) {
    float e = __expf(-fabsf(x));
    float r = __fdividef(1.0f, 1.0f + e);
    float p = (x >= 0.0f) ? r : 1.0f - r;
    float q = 1.0f - p;
    float sp = fmaxf(x, 0.0f) + __logf(1.0f + e);
    return 0.25f * (sp - x) * q * q;
}
__device__ __forceinline__ float softplusf(float x) {
    float e = __expf(-fabsf(x));
    return fmaxf(x, 0.0f) + __logf(1.0f + e);
}

// grid coordinate, bitwise-matching reference: (i + 0.5f) / N, rn division.
__device__ __forceinline__ float gcoord(int i, float fN) {
    return __fdiv_rn((float)i + 0.5f, fN);
}

__device__ __forceinline__ float blockReduceSumF(float v) {
    __shared__ float sh[32];
    int lane = threadIdx.x & 31, wid = threadIdx.x >> 5;
#pragma unroll
    for (int o = 16; o; o >>= 1) v += __shfl_down_sync(0xffffffffu, v, o);
    if (lane == 0) sh[wid] = v;
    __syncthreads();
    int nw = (blockDim.x + 31) >> 5;
    v = (threadIdx.x < nw) ? sh[threadIdx.x] : 0.0f;
    __syncthreads();
    if (wid == 0) {
#pragma unroll
        for (int o = 16; o; o >>= 1) v += __shfl_down_sync(0xffffffffu, v, o);
    }
    return v;
}

// ---------------- kernel 1: bulk focal0 stream (logits + objn, verify) -----
// (unchanged from Round 10)

__global__ __launch_bounds__(256) void k_bulk(
    const float* __restrict__ logits, long long total,
    const float* __restrict__ objn, int objn_n,
    const float* __restrict__ loc,
    const int* __restrict__ ghp, const int* __restrict__ gwp, int L)
{
    {
        int l = blockIdx.x * 256 + threadIdx.x;
        if (l < L && blockIdx.x * 256 < L) {
            int bad = 0;
            if (ghp == nullptr || gwp == nullptr) bad = 1;
            else {
                int W = *gwp, H = *ghp;
                if (W <= 0 || H <= 0 || W > MAX_WH || H > MAX_WH ||
                    (long long)W * H != L) bad = 1;
                else {
                    float2 p = reinterpret_cast<const float2*>(loc)[l];
                    int x = l % W, y = l / W;
                    if (p.x != gcoord(x, (float)W) ||
                        p.y != gcoord(y, (float)H)) bad = 1;
                }
            }
            if (__any_sync(__activemask(), bad)) {
                if ((threadIdx.x & 31) == 0) atomicAnd(&g_ok, 0);
            }
        }
    }

    long long tid    = (long long)blockIdx.x * 256 + threadIdx.x;
    long long stride = (long long)gridDim.x * 256;
    long long n4     = total >> 2;
    const float4* lg4 = reinterpret_cast<const float4*>(logits);

    float a0 = 0.f, a1 = 0.f, a2 = 0.f, a3 = 0.f;
    long long i = tid;
    for (; i + 7 * stride < n4; i += 8 * stride) {
        float4 v0 = lg4[i];
        float4 v1 = lg4[i + stride];
        float4 v2 = lg4[i + 2 * stride];
        float4 v3 = lg4[i + 3 * stride];
        float4 v4 = lg4[i + 4 * stride];
        float4 v5 = lg4[i + 5 * stride];
        float4 v6 = lg4[i + 6 * stride];
        float4 v7 = lg4[i + 7 * stride];
        a0 += focal0(v0.x) + focal0(v0.y) + focal0(v0.z) + focal0(v0.w);
        a1 += focal0(v1.x) + focal0(v1.y) + focal0(v1.z) + focal0(v1.w);
        a2 += focal0(v2.x) + focal0(v2.y) + focal0(v2.z) + focal0(v2.w);
        a3 += focal0(v3.x) + focal0(v3.y) + focal0(v3.z) + focal0(v3.w);
        a0 += focal0(v4.x) + focal0(v4.y) + focal0(v4.z) + focal0(v4.w);
        a1 += focal0(v5.x) + focal0(v5.y) + focal0(v5.z) + focal0(v5.w);
        a2 += focal0(v6.x) + focal0(v6.y) + focal0(v6.z) + focal0(v6.w);
        a3 += focal0(v7.x) + focal0(v7.y) + focal0(v7.z) + focal0(v7.w);
    }
    for (; i < n4; i += stride) {
        float4 v = lg4[i];
        a0 += focal0(v.x) + focal0(v.y) + focal0(v.z) + focal0(v.w);
    }
    float accl = (a0 + a1) + (a2 + a3);
    if (tid == 0) {
        for (long long k = n4 << 2; k < total; k++) accl += focal0(logits[k]);
    }

    float acco = 0.0f;
    {
        const float4* ob4 = reinterpret_cast<const float4*>(objn);
        int on4 = objn_n >> 2;
        for (long long k = tid; k < on4; k += stride) {
            float4 v = ob4[k];
            acco += focal0(v.x) + focal0(v.y) + focal0(v.z) + focal0(v.w);
        }
        if (tid == 0) {
            for (int k = on4 << 2; k < objn_n; k++) acco += focal0(objn[k]);
        }
    }

    float r;
    r = blockReduceSumF(accl);
    if (threadIdx.x == 0) atomicAdd(&g_acc[1], (double)r);
    r = blockReduceSumF(acco);
    if (threadIdx.x == 0) atomicAdd(&g_acc[0], (double)r);
}

// ---------------- kernel 2: positives, 4 boxes/block + finalize ------------
// grid = (ceil(M/4), B), 256 threads. Thread t<196: box q=t/49, cell c=t%49.

__global__ __launch_bounds__(256) void k_pos3(
    const float* __restrict__ boxes,     // (B,L,4)
    const float* __restrict__ deltas,    // (B,L,4)
    const float* __restrict__ logits,    // (B,L,C)
    const float* __restrict__ objn,      // (B,L)
    const float* __restrict__ ctrn,      // (B,L)
    const float* __restrict__ loc,       // (L,2)
    const float* __restrict__ gt_boxes,  // (B,M,4)
    const int*   __restrict__ gt_labels, // (B,M)
    const int* __restrict__ ghp, const int* __restrict__ gwp,
    int B, int M, int L, int C, float* __restrict__ out)
{
    int b   = blockIdx.y;
    int tid = threadIdx.x;

    __shared__ float gxs[MAX_WH], gys[MAX_WH];
    __shared__ float sx1[MAX_M], sy1[MAX_M], sx2[MAX_M], sy2[MAX_M];
    __shared__ float scx[MAX_M], scy[MAX_M], sarea[MAX_M];
    __shared__ int   slab[MAX_M], sbest[MAX_M], sany[MAX_M];
    __shared__ int   silo[MAX_M], sihi[MAX_M], sjlo[MAX_M], sjhi[MAX_M];
    __shared__ int   sicg[MAX_M], sjcg[MAX_M];

    int gok = g_ok;
    int W = 0, H = 0;
    if (gwp && ghp) { W = *gwp; H = *ghp; }
    if (!gok) { W = 0; H = 0; }

    const float2* loc2 = reinterpret_cast<const float2*>(loc);
    for (int i = tid; i < W; i += 256) gxs[i] = loc2[i].x;
    for (int j = tid; j < H; j += 256) gys[j] = loc2[(size_t)j * W].y;

    float gw = (gwp) ? (float)(*gwp) : sqrtf((float)L);
    float gh = (ghp) ? (float)(*ghp) : sqrtf((float)L);
    float rx = 1.0f / gw, ry = 1.0f / gh;

    // ---- per-box prep for ALL boxes of batch b (one box per thread) -------
    if (tid < M) {
        int m = tid;
        float4 gb = reinterpret_cast<const float4*>(gt_boxes)[b * M + m];
        float cx = gb.x, cy = gb.y, w = gb.z, h = gb.w;
        float x1 = cx - w * 0.5f, y1 = cy - h * 0.5f;
        float x2 = cx + w * 0.5f, y2 = cy + h * 0.5f;
        sx1[m] = x1; sy1[m] = y1; sx2[m] = x2; sy2[m] = y2;
        scx[m] = cx; scy[m] = cy; sarea[m] = w * h;
        slab[m] = gt_labels[b * M + m];

        if (gok) {
            float fW = (float)W, fH = (float)H;
            int ilo = (int)floorf(x1 * fW - 0.5f) + 1;
            ilo = max(0, min(ilo, W));
            while (ilo > 0 && gxs[ilo - 1] > x1) ilo--;
            while (ilo < W && !(gxs[ilo] > x1)) ilo++;
            int ihi = (int)ceilf(x2 * fW - 0.5f) - 1;
            ihi = max(-1, min(ihi, W - 1));
            while (ihi < W - 1 && gxs[ihi + 1] < x2) ihi++;
            while (ihi >= 0 && !(gxs[ihi] < x2)) ihi--;
            int jlo = (int)floorf(y1 * fH - 0.5f) + 1;
            jlo = max(0, min(jlo, H));
            while (jlo > 0 && gys[jlo - 1] > y1) jlo--;
            while (jlo < H && !(gys[jlo] > y1)) jlo++;
            int jhi = (int)ceilf(y2 * fH - 0.5f) - 1;
            jhi = max(-1, min(jhi, H - 1));
            while (jhi < H - 1 && gys[jhi + 1] < y2) jhi++;
            while (jhi >= 0 && !(gys[jhi] < y2)) jhi--;

            bool anyin = (ilo <= ihi) && (jlo <= jhi);
            int icg = (int)floorf(cx * fW - 0.5f);
            int jcg = (int)floorf(cy * fH - 0.5f);

            bool anyx = false, anyy = false;
            if (anyin) {
                for (int i = max(ilo, icg - 3); i <= min(ihi, icg + 3); i++)
                    anyx |= (fabsf(gxs[i] - cx) <= rx);
                for (int j = max(jlo, jcg - 3); j <= min(jhi, jcg + 3); j++)
                    anyy |= (fabsf(gys[j] - cy) <= ry);
            }
            bool anyc = anyin && anyx && anyy;

            int ailo, aihi, ajlo, ajhi;
            if (anyin) { ailo = ilo; aihi = ihi; ajlo = jlo; ajhi = jhi; }
            else       { ailo = 0;   aihi = W-1; ajlo = 0;   ajhi = H-1; }
            int ic = max(ailo, min(icg, aihi));
            int jc = max(ajlo, min(jcg, ajhi));
            int ii0 = max(ailo, ic - 2), ii1 = min(aihi, ic + 2);
            int jj0 = max(ajlo, jc - 2), jj1 = min(ajhi, jc + 2);
            unsigned long long bk = ~0ull;
            for (int j = jj0; j <= jj1; j++) {
                float dy = gys[j] - cy;
                float dy2 = __fmul_rn(dy, dy);
                for (int i = ii0; i <= ii1; i++) {
                    float dx = gxs[i] - cx;
                    float dist = __fadd_rn(__fmul_rn(dx, dx), dy2);
                    unsigned long long key =
                        ((unsigned long long)__float_as_uint(dist) << 32) |
                        (unsigned int)(j * W + i);
                    bk = min(bk, key);
                }
            }
            sany[m]  = anyc ? 1 : 0;
            sbest[m] = (int)(bk & 0xffffffffu);
            silo[m] = ilo; sihi[m] = ihi; sjlo[m] = jlo; sjhi[m] = jhi;
            sicg[m] = icg; sjcg[m] = jcg;
        } else {
            // generic fallback: serial scan (correct; never taken on valid input)
            bool anyc = false, anyin = false;
            float bd_in = 3.0e38f;  int bi_in = 0;
            float bd_all = 3.0e38f; int bi_all = 0;
            for (int ll = 0; ll < L; ll++) {
                float2 p = loc2[ll];
                float lx = p.x, ly = p.y;
                bool inb = (lx > x1) && (ly > y1) && (lx < x2) && (ly < y2);
                float dx = lx - cx, dy = ly - cy;
                float dist = __fadd_rn(__fmul_rn(dx, dx), __fmul_rn(dy, dy));
                bool inc = (fabsf(dx) <= rx) && (fabsf(dy) <= ry);
                anyc  |= (inb && inc);
                anyin |= inb;
                if (dist < bd_all) { bd_all = dist; bi_all = ll; }
                if (inb && dist < bd_in) { bd_in = dist; bi_in = ll; }
            }
            sany[m]  = anyc ? 1 : 0;
            sbest[m] = anyin ? bi_in : bi_all;
        }
    }
    __syncthreads();

    float t_obj = 0.f, t_cls = 0.f, t_ctr = 0.f, t_l1 = 0.f, t_giou = 0.f, t_w = 0.f;

    auto winner_of = [&](int l, float lx, float ly) -> int {
        int am = -1;
        float barea = 3.0e38f;
        for (int m = 0; m < M; m++) {
            bool inb = (lx > sx1[m]) && (ly > sy1[m]) && (lx < sx2[m]) && (ly < sy2[m]);
            bool inc = (fabsf(lx - scx[m]) <= rx) && (fabsf(ly - scy[m]) <= ry);
            bool cand = inb && inc;
            bool eff = sany[m] ? cand : (l == sbest[m]);
            if (eff && sarea[m] < barea) { barea = sarea[m]; am = m; }
        }
        return am;
    };

    auto do_pos = [&](int l, float lx, float ly, int am) {
        int bl = b * L + l;
        float ox = objn[bl];
        t_obj += focal1(ox) - focal0(ox);

        float ax1 = sx1[am], ay1 = sy1[am], ax2 = sx2[am], ay2 = sy2[am];
        float lt = fmaxf(lx - ax1, 1e-6f), tt = fmaxf(ly - ay1, 1e-6f);
        float rt = fmaxf(ax2 - lx, 1e-6f), bt = fmaxf(ay2 - ly, 1e-6f);

        float hor = __fdividef(fminf(lt, rt), fmaxf(fmaxf(lt, rt), 1e-6f));
        float ver = __fdividef(fminf(tt, bt), fmaxf(fmaxf(tt, bt), 1e-6f));
        float ctr_t = sqrtf(fmaxf(hor * ver, 0.0f));
        float wgt = fmaxf(ctr_t, 0.1f);
        t_w += wgt;

        float cxv = ctrn[bl];
        t_ctr += (softplusf(cxv) - cxv * ctr_t) * wgt;

        float4 bd = reinterpret_cast<const float4*>(deltas)[bl];
        float d0 = fabsf(bd.x - lt), d1 = fabsf(bd.y - tt);
        float d2 = fabsf(bd.z - rt), d3 = fabsf(bd.w - bt);
        float s0 = (d0 < 0.1f) ? 5.0f * d0 * d0 : d0 - 0.05f;
        float s1 = (d1 < 0.1f) ? 5.0f * d1 * d1 : d1 - 0.05f;
        float s2 = (d2 < 0.1f) ? 5.0f * d2 * d2 : d2 - 0.05f;
        float s3 = (d3 < 0.1f) ? 5.0f * d3 * d3 : d3 - 0.05f;
        t_l1 += 0.25f * (s0 + s1 + s2 + s3) * wgt;

        float4 pb = reinterpret_cast<const float4*>(boxes)[bl];
        float px1 = pb.x, py1 = pb.y, px2 = pb.z, py2 = pb.w;
        float ix1 = fmaxf(px1, ax1), iy1 = fmaxf(py1, ay1);
        float ix2 = fminf(px2, ax2), iy2 = fminf(py2, ay2);
        float inter = fmaxf(ix2 - ix1, 0.0f) * fmaxf(iy2 - iy1, 0.0f);
        float ap = fmaxf(px2 - px1, 0.0f) * fmaxf(py2 - py1, 0.0f);
        float ag = fmaxf(ax2 - ax1, 0.0f) * fmaxf(ay2 - ay1, 0.0f);
        float uni = ap + ag - inter;
        float iou = __fdividef(inter, fmaxf(uni, 1e-6f));
        float hx1 = fminf(px1, ax1), hy1 = fminf(py1, ay1);
        float hx2 = fmaxf(px2, ax2), hy2 = fmaxf(py2, ay2);
        float hull = fmaxf(hx2 - hx1, 0.0f) * fmaxf(hy2 - hy1, 0.0f);
        float giou = iou - __fdividef(hull - uni, fmaxf(hull, 1e-6f));
        t_giou += (1.0f - giou) * wgt;

        float xl = logits[(size_t)bl * C + slab[am]];
        t_cls += focal1(xl) - focal0(xl);
    };

    if (gok) {
        if (tid < 49 * BOX_PER_BLK) {
            int q = tid / 49;
            int c = tid - q * 49;
            int m = blockIdx.x * BOX_PER_BLK + q;
            if (m < M) {
                if (sany[m]) {
                    int i = sicg[m] + (c % 7) - 3;
                    int j = sjcg[m] + (c / 7) - 3;
                    if (i >= silo[m] && i <= sihi[m] &&
                        j >= sjlo[m] && j <= sjhi[m]) {
                        float lx = gxs[i], ly = gys[j];
                        if (fabsf(lx - scx[m]) <= rx &&
                            fabsf(ly - scy[m]) <= ry) {
                            int l = j * W + i;
                            if (winner_of(l, lx, ly) == m) do_pos(l, lx, ly, m);
                        }
                    }
                } else if (c == 0) {
                    int l = sbest[m];
                    int i = l % W, j = l / W;
                    float lx = gxs[i], ly = gys[j];
                    if (winner_of(l, lx, ly) == m) do_pos(l, lx, ly, m);
                }
            }
        }
    } else {
        // generic fallback: blocks with blockIdx.x==0 scan all L for batch b
        if (blockIdx.x == 0) {
            for (int l = tid; l < L; l += 256) {
                float2 p = loc2[l];
                int am = winner_of(l, p.x, p.y);
                if (am >= 0) do_pos(l, p.x, p.y, am);
            }
        }
    }

    // ---- combined block reduction (one __syncthreads round) --------------
    {
        __shared__ float sh[6][8];
        int lane = tid & 31, wid = tid >> 5;
        float v0 = t_obj, v1 = t_cls, v2 = t_ctr, v3 = t_l1, v4 = t_giou, v5 = t_w;
#pragma unroll
        for (int o = 16; o; o >>= 1) {
            v0 += __shfl_down_sync(0xffffffffu, v0, o);
            v1 += __shfl_down_sync(0xffffffffu, v1, o);
            v2 += __shfl_down_sync(0xffffffffu, v2, o);
            v3 += __shfl_down_sync(0xffffffffu, v3, o);
            v4 += __shfl_down_sync(0xffffffffu, v4, o);
            v5 += __shfl_down_sync(0xffffffffu, v5, o);
        }
        if (lane == 0) {
            sh[0][wid] = v0; sh[1][wid] = v1; sh[2][wid] = v2;
            sh[3][wid] = v3; sh[4][wid] = v4; sh[5][wid] = v5;
        }
        __syncthreads();
        if (wid == 0 && lane < 6) {
            float s = 0.0f;
#pragma unroll
            for (int k = 0; k < 8; k++) s += sh[lane][k];
            atomicAdd(&g_acc[lane], (double)s);
        }
    }

    // ---- last block finalizes + resets globals for the next replay --------
    if (tid == 0) {
        __threadfence();
        unsigned int total = gridDim.x * gridDim.y;
        unsigned int prev = atomicAdd(&g_done, 1u);
        if (prev == total - 1) {
            volatile double* acc = g_acc;
            double nBL  = (double)B * (double)L;
            double nBLC = nBL * (double)C;
            double wsum = acc[5];
            double inv_w = (wsum != 0.0) ? (1.0 / wsum) : 0.0;
            double loss = 1.0 * acc[0] / nBL
                        + 1.5 * acc[1] / nBLC
                        + 0.5 * acc[2] * inv_w
                        + 5.0 * acc[3] * inv_w
                        + 2.0 * acc[4] * inv_w;
            out[0] = (float)loss;
            for (int k = 0; k < 8; k++) g_acc[k] = 0.0;
            g_done = 0u;
            g_ok = 1;
            __threadfence();
        }
    }
}

// ---------------- launch ---------------------------------------------------

extern "C" void kernel_launch(void* const* d_in, const int* in_sizes, int n_in,
                              void* d_out, int out_size)
{
    const float* boxes  = (const float*)d_in[0];
    const float* deltas = (const float*)d_in[1];
    const float* logits = (const float*)d_in[2];
    const float* objn   = (const float*)d_in[3];
    const float* ctrn   = (const float*)d_in[4];
    const float* loc    = (const float*)d_in[5];
    const float* gtb    = (const float*)d_in[6];
    const int*   gtl    = (const int*)d_in[7];
    const int*   ghp    = (n_in > 8) ? (const int*)d_in[8] : nullptr;
    const int*   gwp    = (n_in > 9) ? (const int*)d_in[9] : nullptr;

    int L = in_sizes[5] / 2;
    int B = in_sizes[3] / L;
    int M = in_sizes[7] / B;
    int C = in_sizes[2] / in_sizes[3];

    k_bulk<<<2560, 256>>>(logits, (long long)in_sizes[2],
                          objn, in_sizes[3], loc, ghp, gwp, L);
    dim3 gpos((M + BOX_PER_BLK - 1) / BOX_PER_BLK, B);
    k_pos3<<<gpos, 256>>>(boxes, deltas, logits, objn, ctrn, loc, gtb, gtl,
                          ghp, gwp, B, M, L, C, (float*)d_out);
}